// round 6
// baseline (speedup 1.0000x reference)
#include <cuda_runtime.h>

#define Bn 32
#define Sn 2048
#define Dn 1024
#define K1S 32          // S-splits in K1 / chunks in K3 (64 rows each)
#define RPS 64          // rows per split/chunk
#define RPW 8           // rows per warp in K3 (8 warps * 8 rows = 64)

// ---- scratch (device globals; no allocations allowed) ----
__device__ float g_ysp[K1S * Bn * Dn];   // [split][b][d] partial column sums (4 MB)
__device__ float g_ys[Bn * Dn];          // column sums of E over S
__device__ float g_u[Bn * Dn];           // u[b,d] = sum_e W[d,e]*ys_sum[b,e]
__device__ float g_acc[Bn * K1S * Dn];   // per-(b,chunk) partial zs (4 MB)
__device__ float g_m[Bn * K1S];          // per-(b,chunk) softmax max
__device__ float g_Z[Bn * K1S];          // per-(b,chunk) softmax denom (at g_m)
__device__ int   g_mode;                 // mask dtype: 0=u8 1=i32 2=f32

// ===================== K1: partial column sums of E =====================
// grid 1024 = (b:32) x (split:32); 256 threads, thread t owns float4 col t.
// All blocks co-resident (single wave) -> ~1% imbalance. Also probes mask dtype.
__global__ __launch_bounds__(256) void k1_colsum(const float* __restrict__ E,
                                                 const unsigned int* __restrict__ maskw) {
    int bx = blockIdx.x;
    int b  = bx >> 5;
    int sh = bx & 31;
    int t  = threadIdx.x;

    if (bx == 0 && t == 0) {
        bool allLe1 = true, allF = true;
        #pragma unroll 4
        for (int i = 0; i < 64; i++) {
            unsigned int v = maskw[i];
            if (v > 1u) allLe1 = false;
            if (v != 0u && v != 0x3F800000u) allF = false;
        }
        g_mode = allLe1 ? 1 : (allF ? 2 : 0);
    }

    const float4* p = reinterpret_cast<const float4*>(E)
                    + (size_t)(b * Sn + sh * RPS) * 256 + t;
    float4 a0 = make_float4(0.f,0.f,0.f,0.f), a1 = a0, a2 = a0, a3 = a0;
    #pragma unroll 4
    for (int s = 0; s < RPS; s += 4) {
        float4 v0 = p[(size_t)(s + 0) * 256];
        float4 v1 = p[(size_t)(s + 1) * 256];
        float4 v2 = p[(size_t)(s + 2) * 256];
        float4 v3 = p[(size_t)(s + 3) * 256];
        a0.x += v0.x; a0.y += v0.y; a0.z += v0.z; a0.w += v0.w;
        a1.x += v1.x; a1.y += v1.y; a1.z += v1.z; a1.w += v1.w;
        a2.x += v2.x; a2.y += v2.y; a2.z += v2.z; a2.w += v2.w;
        a3.x += v3.x; a3.y += v3.y; a3.z += v3.z; a3.w += v3.w;
    }
    float4 s4 = make_float4((a0.x + a1.x) + (a2.x + a3.x),
                            (a0.y + a1.y) + (a2.y + a3.y),
                            (a0.z + a1.z) + (a2.z + a3.z),
                            (a0.w + a1.w) + (a2.w + a3.w));
    reinterpret_cast<float4*>(g_ysp)[(size_t)(sh * Bn + b) * 256 + t] = s4;
}

// ===================== K1r: reduce 32 slices -> g_ys; zero g_u ==============
// grid 32 (per b), 256 threads (float4 col each).
__global__ __launch_bounds__(256) void k1_reduce() {
    int b = blockIdx.x, t = threadIdx.x;
    const float4* base = reinterpret_cast<const float4*>(g_ysp);
    float4 s = make_float4(0.f,0.f,0.f,0.f);
    #pragma unroll
    for (int c = 0; c < K1S; c++) {
        float4 v = base[(size_t)(c * Bn + b) * 256 + t];
        s.x += v.x; s.y += v.y; s.z += v.z; s.w += v.w;
    }
    reinterpret_cast<float4*>(g_ys)[b * 256 + t] = s;
    reinterpret_cast<float4*>(g_u)[b * 256 + t] = make_float4(0.f,0.f,0.f,0.f);
}

// ===================== K2: u[b,d] = sum_e W[d,e] * ys_sum[b,e] =====================
// grid 256 = (dtile:16 of 64 d) x (esplit:16 of 64 e), atomicAdd partials.
__global__ __launch_bounds__(256) void k2_u(const float* __restrict__ W) {
    __shared__ float Ws[64 * 65];   // padded rows: conflict-free column reads
    __shared__ float Ys[32 * 64];
    int dt = blockIdx.x >> 4, es = blockIdx.x & 15;
    int d0 = dt * 64, e0 = es * 64;
    int t = threadIdx.x;
    #pragma unroll
    for (int k = 0; k < 16; k++) {
        int idx = t + k * 256;
        int r = idx >> 6, c = idx & 63;
        Ws[r * 65 + c] = W[(size_t)(d0 + r) * Dn + e0 + c];
    }
    #pragma unroll
    for (int k = 0; k < 8; k++) {
        int idx = t + k * 256;
        int b = idx >> 6, c = idx & 63;
        Ys[b * 64 + c] = g_ys[b * Dn + e0 + c];
    }
    __syncthreads();
    int bg = t >> 5, dg = t & 31;
    float a00=0,a01=0,a10=0,a11=0,a20=0,a21=0,a30=0,a31=0;
    #pragma unroll 8
    for (int c = 0; c < 64; c++) {
        float w0 = Ws[dg * 65 + c];
        float w1 = Ws[(dg + 32) * 65 + c];
        float y0 = Ys[(bg * 4 + 0) * 64 + c];
        float y1 = Ys[(bg * 4 + 1) * 64 + c];
        float y2 = Ys[(bg * 4 + 2) * 64 + c];
        float y3 = Ys[(bg * 4 + 3) * 64 + c];
        a00 += y0 * w0; a01 += y0 * w1;
        a10 += y1 * w0; a11 += y1 * w1;
        a20 += y2 * w0; a21 += y2 * w1;
        a30 += y3 * w0; a31 += y3 * w1;
    }
    atomicAdd(&g_u[(bg * 4 + 0) * Dn + d0 + dg],      a00);
    atomicAdd(&g_u[(bg * 4 + 0) * Dn + d0 + dg + 32], a01);
    atomicAdd(&g_u[(bg * 4 + 1) * Dn + d0 + dg],      a10);
    atomicAdd(&g_u[(bg * 4 + 1) * Dn + d0 + dg + 32], a11);
    atomicAdd(&g_u[(bg * 4 + 2) * Dn + d0 + dg],      a20);
    atomicAdd(&g_u[(bg * 4 + 2) * Dn + d0 + dg + 32], a21);
    atomicAdd(&g_u[(bg * 4 + 3) * Dn + d0 + dg],      a30);
    atomicAdd(&g_u[(bg * 4 + 3) * Dn + d0 + dg + 32], a31);
}

// ===================== K3: fused f + online softmax + partial zs =====================
// grid 1024 = (b:32) x (chunk:32 of 64 rows); 8 warps, warp owns 8 rows.
// Rows are processed back-to-front so K1's L2-resident strip tails hit first.
__global__ __launch_bounds__(256, 2) void k3_main(
    const float* __restrict__ E, const void* __restrict__ maskp,
    float* __restrict__ fout)
{
    __shared__ float sAcc[8][1024];
    __shared__ float sM[8], sZ[8];

    int t = threadIdx.x, w = t >> 5, lane = t & 31;
    int bx = blockIdx.x;
    int b = bx >> 5, chunk = bx & 31;
    int mode = g_mode;

    // lane-resident u slice, scaled by 1/S (folds the mean)
    const float4* u4 = reinterpret_cast<const float4*>(g_u + b * Dn);
    float4 u[8];
    const float invS = 1.0f / 2048.0f;
    #pragma unroll
    for (int j = 0; j < 8; j++) {
        float4 v = u4[j * 32 + lane];
        u[j] = make_float4(v.x * invS, v.y * invS, v.z * invS, v.w * invS);
    }

    float4 acc[8];
    #pragma unroll
    for (int j = 0; j < 8; j++) acc[j] = make_float4(0.f,0.f,0.f,0.f);
    float m = -1.0e30f, Z = 0.f;

    int sBase = chunk * RPS + (7 - w) * RPW;   // reversed warp order
    const float4* E4 = reinterpret_cast<const float4*>(E);

    for (int i = RPW - 1; i >= 0; i--) {       // reversed row order
        int s = sBase + i;
        const float4* row = E4 + (size_t)(b * Sn + s) * 256;
        float4 r[8];
        float dot = 0.f;
        #pragma unroll
        for (int j = 0; j < 8; j++) {
            r[j] = row[j * 32 + lane];
            dot += r[j].x * u[j].x + r[j].y * u[j].y + r[j].z * u[j].z + r[j].w * u[j].w;
        }
        #pragma unroll
        for (int o = 16; o; o >>= 1) dot += __shfl_xor_sync(0xffffffffu, dot, o);

        int midx = b * Sn + s;
        bool mk;
        if (mode == 1)      mk = ((const int*)maskp)[midx] != 0;
        else if (mode == 2) mk = ((const float*)maskp)[midx] != 0.f;
        else                mk = ((const unsigned char*)maskp)[midx] != 0;
        float f = mk ? dot : -1.0e9f;
        if (lane == 0) fout[midx] = f;         // raw logit; K4 normalizes

        if (f > m) {
            float sc = __expf(m - f);
            #pragma unroll
            for (int j = 0; j < 8; j++) {
                acc[j].x *= sc; acc[j].y *= sc; acc[j].z *= sc; acc[j].w *= sc;
            }
            Z *= sc;
            m = f;
        }
        float p = __expf(f - m);
        Z += p;
        #pragma unroll
        for (int j = 0; j < 8; j++) {
            acc[j].x += p * r[j].x; acc[j].y += p * r[j].y;
            acc[j].z += p * r[j].z; acc[j].w += p * r[j].w;
        }
    }

    // combine 8 warps -> one chunk partial
    float4* sA = reinterpret_cast<float4*>(&sAcc[w][0]);
    #pragma unroll
    for (int j = 0; j < 8; j++) sA[j * 32 + lane] = acc[j];
    if (lane == 0) { sM[w] = m; sZ[w] = Z; }
    __syncthreads();

    float M = sM[0];
    #pragma unroll
    for (int k = 1; k < 8; k++) M = fmaxf(M, sM[k]);
    float sc[8];
    #pragma unroll
    for (int k = 0; k < 8; k++) sc[k] = __expf(sM[k] - M);
    if (t == 0) {
        float Zb = 0.f;
        #pragma unroll
        for (int k = 0; k < 8; k++) Zb += sZ[k] * sc[k];
        g_Z[bx] = Zb;
        g_m[bx] = M;
    }
    float4 v = make_float4(0.f,0.f,0.f,0.f);
    #pragma unroll
    for (int k = 0; k < 8; k++) {
        float4 a = reinterpret_cast<const float4*>(&sAcc[k][0])[t];
        v.x += sc[k] * a.x; v.y += sc[k] * a.y;
        v.z += sc[k] * a.z; v.w += sc[k] * a.w;
    }
    reinterpret_cast<float4*>(g_acc)[(size_t)bx * 256 + t] = v;
}

// ===================== K4: merge 32 chunks, write zs, normalize f ==================
// grid 256 = (b:32) x (part:8); 256 threads.
__global__ __launch_bounds__(256) void k4_final(float* __restrict__ out) {
    int bx = blockIdx.x;
    int b = bx >> 3, j = bx & 7;
    int t = threadIdx.x;

    float M = -1.0e30f;
    #pragma unroll
    for (int c = 0; c < K1S; c++) M = fmaxf(M, g_m[b * K1S + c]);
    float sc[K1S];
    float Z = 0.f;
    #pragma unroll
    for (int c = 0; c < K1S; c++) {
        sc[c] = __expf(g_m[b * K1S + c] - M);
        Z += g_Z[b * K1S + c] * sc[c];
    }
    float rinv = 1.0f / Z;

    if (t < 128) {
        int col = j * 128 + t;
        float s = 0.f;
        #pragma unroll
        for (int c = 0; c < K1S; c++)
            s += sc[c] * g_acc[((size_t)(b * K1S + c) << 10) + col];
        out[b * Dn + col] = s * rinv;
    }

    float* f = out + Bn * Dn;
    int idx = b * Sn + j * 256 + t;
    f[idx] = __expf(f[idx] - M) * rinv;
}

extern "C" void kernel_launch(void* const* d_in, const int* in_sizes, int n_in,
                              void* d_out, int out_size) {
    const float* E    = (const float*)d_in[0];
    const void*  mask = d_in[1];
    const float* W    = (const float*)d_in[2];
    float* out = (float*)d_out;

    k1_colsum<<<1024, 256>>>(E, (const unsigned int*)mask);
    k1_reduce<<<32, 256>>>();
    k2_u     <<<256, 256>>>(W);
    k3_main  <<<1024, 256>>>(E, mask, out + Bn * Dn);
    k4_final <<<256, 256>>>(out);
}